// round 2
// baseline (speedup 1.0000x reference)
#include <cuda_runtime.h>

#define NINT 50000
#define NLANE 400000
#define EPO 400000
#define EADJ 200000
#define CH 64
#define HC 256
#define G3 192

// ---------------- scratch (static device globals; no allocation) ----------------
__device__ float g_e_int[(size_t)NINT * CH];
__device__ float g_e_lane[(size_t)NLANE * CH];
__device__ float g_hs[(size_t)NLANE * HC];      // reused for adj (smaller)
__device__ float g_as[(size_t)NLANE * 4];
__device__ float g_ad[(size_t)NINT * 4];
__device__ float g_den[(size_t)NINT * 4];
__device__ float g_ex[(size_t)EPO * 4];
__device__ float g_accum[(size_t)NINT * HC];
__device__ float g_gi[(size_t)NINT * G3];
__device__ float g_gh[(size_t)NINT * G3];
__device__ float g_WihT[HC * G3];
__device__ float g_WhhT[CH * G3];
__device__ float g_Mfold[CH * 4 * 2];

// ---------------- encoders: E = relu(X[M,K] @ W[K,64] + b) ----------------
template <int K>
__global__ void encoder_kernel(const float* __restrict__ X, const float* __restrict__ W,
                               const float* __restrict__ b, float* __restrict__ Eo, int M) {
    __shared__ float Ws[K * 64];
    __shared__ float bs[64];
    __shared__ float Xs[4][K];
    int t = threadIdx.x;
    for (int i = t; i < K * 64; i += 256) Ws[i] = W[i];
    if (t < 64) bs[t] = b[t];
    int row0 = blockIdx.x * 4;
    for (int i = t; i < 4 * K; i += 256) {
        int r = i / K, k = i % K;
        int gr = row0 + r;
        Xs[r][k] = (gr < M) ? X[(size_t)gr * K + k] : 0.f;
    }
    __syncthreads();
    int r = t >> 6, c = t & 63;
    float s = bs[c];
#pragma unroll
    for (int k = 0; k < K; k++) s += Xs[r][k] * Ws[k * 64 + c];
    int gr = row0 + r;
    if (gr < M) Eo[(size_t)gr * 64 + c] = fmaxf(s, 0.f);
}

// ---------------- generic GEMM: C[M,N] = A[M,K] @ B[K,N] ----------------
// 64x64 tile per block, 256 threads, 4x4 micro-tile. Optional: per-row
// attention reduction per N-tile (each 64-col tile == one head) into aout[M,4].
template <bool WRITE_C, bool ATT, bool RELUA>
__global__ void gemm_kernel(const float* __restrict__ A, const float* __restrict__ B,
                            float* __restrict__ C, const float* __restrict__ att,
                            float* __restrict__ aout, int M, int K, int N) {
    __shared__ float As[64][65];
    __shared__ float Bs[64][64];
    __shared__ float attsm[64];
    int t = threadIdx.x;
    int tx = t & 15, ty = t >> 4;
    int m0 = blockIdx.y << 6, n0 = blockIdx.x << 6;
    if (ATT && t < 64) attsm[t] = att[n0 + t];
    float acc[4][4];
#pragma unroll
    for (int i = 0; i < 4; i++)
#pragma unroll
        for (int j = 0; j < 4; j++) acc[i][j] = 0.f;

    for (int k0 = 0; k0 < K; k0 += 64) {
#pragma unroll
        for (int it = 0; it < 16; it++) {
            int idx = it * 256 + t;
            int k = idx & 63, m = idx >> 6;
            int gm = m0 + m;
            float v = 0.f;
            if (gm < M) v = A[(size_t)gm * K + k0 + k];
            if (RELUA) v = fmaxf(v, 0.f);
            As[k][m] = v;
        }
#pragma unroll
        for (int it = 0; it < 16; it++) {
            int idx = it * 256 + t;
            int n = idx & 63, k = idx >> 6;
            Bs[k][n] = B[(size_t)(k0 + k) * N + n0 + n];
        }
        __syncthreads();
#pragma unroll 8
        for (int k = 0; k < 64; k++) {
            float4 bv = *(const float4*)&Bs[k][tx << 2];
            float a0 = As[k][(ty << 2) + 0];
            float a1 = As[k][(ty << 2) + 1];
            float a2 = As[k][(ty << 2) + 2];
            float a3 = As[k][(ty << 2) + 3];
            acc[0][0] += a0 * bv.x; acc[0][1] += a0 * bv.y; acc[0][2] += a0 * bv.z; acc[0][3] += a0 * bv.w;
            acc[1][0] += a1 * bv.x; acc[1][1] += a1 * bv.y; acc[1][2] += a1 * bv.z; acc[1][3] += a1 * bv.w;
            acc[2][0] += a2 * bv.x; acc[2][1] += a2 * bv.y; acc[2][2] += a2 * bv.z; acc[2][3] += a2 * bv.w;
            acc[3][0] += a3 * bv.x; acc[3][1] += a3 * bv.y; acc[3][2] += a3 * bv.z; acc[3][3] += a3 * bv.w;
        }
        __syncthreads();
    }

    if (WRITE_C) {
#pragma unroll
        for (int i = 0; i < 4; i++) {
            int gm = m0 + (ty << 2) + i;
            if (gm < M)
                *(float4*)&C[(size_t)gm * N + n0 + (tx << 2)] =
                    make_float4(acc[i][0], acc[i][1], acc[i][2], acc[i][3]);
        }
    }
    if (ATT) {
#pragma unroll
        for (int i = 0; i < 4; i++) {
            float p = acc[i][0] * attsm[(tx << 2) + 0] + acc[i][1] * attsm[(tx << 2) + 1] +
                      acc[i][2] * attsm[(tx << 2) + 2] + acc[i][3] * attsm[(tx << 2) + 3];
            p += __shfl_xor_sync(0xffffffffu, p, 8);
            p += __shfl_xor_sync(0xffffffffu, p, 4);
            p += __shfl_xor_sync(0xffffffffu, p, 2);
            p += __shfl_xor_sync(0xffffffffu, p, 1);
            if (tx == 0) {
                int gm = m0 + (ty << 2) + i;
                if (gm < M) aout[(size_t)gm * 4 + (n0 >> 6)] = p;
            }
        }
    }
}

// ---------------- fold: Mout[k,h] = sum_c Wdst[k, h*64+c] * att[h,c] ----------------
__global__ void fold_att_kernel(const float* __restrict__ W, const float* __restrict__ att,
                                float* __restrict__ Mout) {
    int t = threadIdx.x;  // 256 = 64 k * 4 h
    int k = t >> 2, h = t & 3;
    float s = 0.f;
#pragma unroll
    for (int c = 0; c < 64; c++) s += W[k * 256 + h * 64 + c] * att[h * 64 + c];
    Mout[k * 4 + h] = s;
}

// ---------------- a_d = E[M,64] @ Mfold[64,4] ----------------
__global__ void compute_ad_kernel(const float* __restrict__ E, const float* __restrict__ Mm,
                                  float* __restrict__ ad, int M) {
    __shared__ float Es[64][65];
    __shared__ float Ms[256];
    int t = threadIdx.x;
    Ms[t] = Mm[t];
    int row0 = blockIdx.x * 64;
#pragma unroll
    for (int it = 0; it < 16; it++) {
        int idx = it * 256 + t;
        int k = idx & 63, r = idx >> 6;
        int gr = row0 + r;
        Es[r][k] = (gr < M) ? E[(size_t)gr * 64 + k] : 0.f;
    }
    __syncthreads();
    int r = t >> 2, h = t & 3;
    float s = 0.f;
#pragma unroll
    for (int k = 0; k < 64; k++) s += Es[r][k] * Ms[k * 4 + h];
    int gr = row0 + r;
    if (gr < M) ad[(size_t)gr * 4 + h] = s;
}

// ---------------- zero fill ----------------
__global__ void zero_kernel(float* __restrict__ p, int n) {
    int i = blockIdx.x * blockDim.x + threadIdx.x;
    if (i < n) p[i] = 0.f;
}

// ---------------- accum init: out[i,j] = bias_po[j] + bias_adj[j] ----------------
__global__ void init_accum_kernel(const float* __restrict__ bpo, const float* __restrict__ badj,
                                  float* __restrict__ out, int total) {
    int i = blockIdx.x * blockDim.x + threadIdx.x;
    if (i < total) {
        int j = i & 255;
        out[i] = bpo[j] + badj[j];
    }
}

// ---------------- edge softmax numerator: ex = exp(lrelu(a_s[src]+a_d[dst])) ----------------
__global__ void edge_softmax_kernel(const int* __restrict__ src, const int* __restrict__ dst,
                                    const float* __restrict__ as_, const float* __restrict__ ad_,
                                    float* __restrict__ ex, float* __restrict__ den, int E) {
    int e = blockIdx.x * blockDim.x + threadIdx.x;
    if (e >= E) return;
    int s = src[e], d = dst[e];
    float4 A = *(const float4*)&as_[(size_t)s * 4];
    float4 D = *(const float4*)&ad_[(size_t)d * 4];
    float v0 = A.x + D.x, v1 = A.y + D.y, v2 = A.z + D.z, v3 = A.w + D.w;
    v0 = (v0 > 0.f) ? v0 : 0.2f * v0;
    v1 = (v1 > 0.f) ? v1 : 0.2f * v1;
    v2 = (v2 > 0.f) ? v2 : 0.2f * v2;
    v3 = (v3 > 0.f) ? v3 : 0.2f * v3;
    float e0 = __expf(v0), e1 = __expf(v1), e2 = __expf(v2), e3 = __expf(v3);
    *(float4*)&ex[(size_t)e * 4] = make_float4(e0, e1, e2, e3);
    atomicAdd(&den[d * 4 + 0], e0);
    atomicAdd(&den[d * 4 + 1], e1);
    atomicAdd(&den[d * 4 + 2], e2);
    atomicAdd(&den[d * 4 + 3], e3);
}

__global__ void recip_kernel(float* __restrict__ den, int n) {
    int i = blockIdx.x * blockDim.x + threadIdx.x;
    if (i < n) {
        float d = den[i];
        den[i] = (d > 0.f) ? 1.f / d : 0.f;
    }
}

// ---------------- edge aggregate: out[dst] += hs[src] * w  (one block per edge) ----------------
__global__ void edge_aggregate_kernel(const int* __restrict__ src, const int* __restrict__ dst,
                                      const float* __restrict__ hs, const float* __restrict__ ex,
                                      const float* __restrict__ rden, float* __restrict__ out) {
    int e = blockIdx.x;
    int j = threadIdx.x;  // 256
    int s = src[e], d = dst[e];
    int h = j >> 6;
    float w = ex[(size_t)e * 4 + h] * rden[d * 4 + h];
    float val = hs[(size_t)s * 256 + j] * w;
    atomicAdd(&out[(size_t)d * 256 + j], val);
}

// ---------------- transpose: Wt[c*R + r] = W[r*C + c] ----------------
__global__ void transpose_kernel(const float* __restrict__ W, float* __restrict__ Wt, int R, int C) {
    int i = blockIdx.x * blockDim.x + threadIdx.x;
    if (i < R * C) {
        int r = i / C, c = i % C;
        Wt[c * R + r] = W[i];
    }
}

// ---------------- GRU elementwise ----------------
__global__ void gru_kernel(const float* __restrict__ gi, const float* __restrict__ gh,
                           const float* __restrict__ bih, const float* __restrict__ bhh,
                           const float* __restrict__ h0, float* __restrict__ hnew, int M) {
    int idx = blockIdx.x * blockDim.x + threadIdx.x;
    if (idx >= M * 64) return;
    int row = idx >> 6, c = idx & 63;
    float ir = gi[(size_t)row * 192 + c] + bih[c];
    float iz = gi[(size_t)row * 192 + 64 + c] + bih[64 + c];
    float in = gi[(size_t)row * 192 + 128 + c] + bih[128 + c];
    float hr = gh[(size_t)row * 192 + c] + bhh[c];
    float hz = gh[(size_t)row * 192 + 64 + c] + bhh[64 + c];
    float hn = gh[(size_t)row * 192 + 128 + c] + bhh[128 + c];
    float r = 1.f / (1.f + __expf(-(ir + hr)));
    float z = 1.f / (1.f + __expf(-(iz + hz)));
    float n = tanhf(in + r * hn);
    hnew[idx] = (1.f - z) * n + z * h0[idx];
}

// ---------------- output heads: one warp per row ----------------
__global__ void heads_kernel(const float* __restrict__ hn, const float* __restrict__ Wpi,
                             const float* __restrict__ bpi, const float* __restrict__ Wv,
                             const float* __restrict__ bv, float* __restrict__ logits,
                             float* __restrict__ value, int M) {
    __shared__ float Wp[64 * 8];
    __shared__ float Wvv[64];
    int t = threadIdx.x;  // 256
    for (int i = t; i < 512; i += 256) Wp[i] = Wpi[i];
    if (t < 64) Wvv[t] = Wv[t];
    __syncthreads();
    int warp = t >> 5, lane = t & 31;
    int row = blockIdx.x * 8 + warp;
    if (row >= M) return;
    float h1 = hn[(size_t)row * 64 + lane];
    float h2 = hn[(size_t)row * 64 + 32 + lane];
#pragma unroll
    for (int j = 0; j < 8; j++) {
        float p = h1 * Wp[lane * 8 + j] + h2 * Wp[(lane + 32) * 8 + j];
        p += __shfl_xor_sync(0xffffffffu, p, 16);
        p += __shfl_xor_sync(0xffffffffu, p, 8);
        p += __shfl_xor_sync(0xffffffffu, p, 4);
        p += __shfl_xor_sync(0xffffffffu, p, 2);
        p += __shfl_xor_sync(0xffffffffu, p, 1);
        if (lane == 0) logits[(size_t)row * 8 + j] = p + bpi[j];
    }
    float v = h1 * Wvv[lane] + h2 * Wvv[lane + 32];
    v += __shfl_xor_sync(0xffffffffu, v, 16);
    v += __shfl_xor_sync(0xffffffffu, v, 8);
    v += __shfl_xor_sync(0xffffffffu, v, 4);
    v += __shfl_xor_sync(0xffffffffu, v, 2);
    v += __shfl_xor_sync(0xffffffffu, v, 1);
    if (lane == 0) value[row] = v + bv[0];
}

// ---------------- launch ----------------
extern "C" void kernel_launch(void* const* d_in, const int* in_sizes, int n_in,
                              void* d_out, int out_size) {
    const float* x_int = (const float*)d_in[0];
    const float* x_lane = (const float*)d_in[1];
    const float* h0 = (const float*)d_in[2];
    const float* enc_int_W = (const float*)d_in[3];
    const float* enc_int_b = (const float*)d_in[4];
    const float* enc_lane_W = (const float*)d_in[5];
    const float* enc_lane_b = (const float*)d_in[6];
    const float* Wsrc_po = (const float*)d_in[7];
    const float* Wdst_po = (const float*)d_in[8];
    const float* att_src_po = (const float*)d_in[9];
    const float* att_dst_po = (const float*)d_in[10];
    const float* bias_po = (const float*)d_in[11];
    const float* Wsrc_adj = (const float*)d_in[12];
    const float* Wdst_adj = (const float*)d_in[13];
    const float* att_src_adj = (const float*)d_in[14];
    const float* att_dst_adj = (const float*)d_in[15];
    const float* bias_adj = (const float*)d_in[16];
    const float* gru_W_ih = (const float*)d_in[17];
    const float* gru_W_hh = (const float*)d_in[18];
    const float* gru_b_ih = (const float*)d_in[19];
    const float* gru_b_hh = (const float*)d_in[20];
    const float* W_pi = (const float*)d_in[21];
    const float* b_pi = (const float*)d_in[22];
    const float* W_v = (const float*)d_in[23];
    const float* b_v = (const float*)d_in[24];
    const int* src_po = (const int*)d_in[25];
    const int* dst_po = (const int*)d_in[26];
    const int* src_adj = (const int*)d_in[27];
    const int* dst_adj = (const int*)d_in[28];

    float* out = (float*)d_out;
    float* logits = out;                           // [NINT, 8]
    float* value = out + (size_t)NINT * 8;         // [NINT, 1]
    float* hnew = out + (size_t)NINT * 9;          // [NINT, 64]

    float *e_int, *e_lane, *hs, *as_, *ad_, *den, *ex, *accum, *gi, *gh, *WihT, *WhhT, *Mfold;
    cudaGetSymbolAddress((void**)&e_int, g_e_int);
    cudaGetSymbolAddress((void**)&e_lane, g_e_lane);
    cudaGetSymbolAddress((void**)&hs, g_hs);
    cudaGetSymbolAddress((void**)&as_, g_as);
    cudaGetSymbolAddress((void**)&ad_, g_ad);
    cudaGetSymbolAddress((void**)&den, g_den);
    cudaGetSymbolAddress((void**)&ex, g_ex);
    cudaGetSymbolAddress((void**)&accum, g_accum);
    cudaGetSymbolAddress((void**)&gi, g_gi);
    cudaGetSymbolAddress((void**)&gh, g_gh);
    cudaGetSymbolAddress((void**)&WihT, g_WihT);
    cudaGetSymbolAddress((void**)&WhhT, g_WhhT);
    cudaGetSymbolAddress((void**)&Mfold, g_Mfold);

    // encoders
    encoder_kernel<16><<<(NINT + 3) / 4, 256>>>(x_int, enc_int_W, enc_int_b, e_int, NINT);
    encoder_kernel<12><<<(NLANE + 3) / 4, 256>>>(x_lane, enc_lane_W, enc_lane_b, e_lane, NLANE);

    // small prep
    fold_att_kernel<<<1, 256>>>(Wdst_po, att_dst_po, Mfold);
    fold_att_kernel<<<1, 256>>>(Wdst_adj, att_dst_adj, Mfold + 256);
    init_accum_kernel<<<(NINT * HC + 255) / 256, 256>>>(bias_po, bias_adj, accum, NINT * HC);
    transpose_kernel<<<(192 * 256 + 255) / 256, 256>>>(gru_W_ih, WihT, 192, 256);
    transpose_kernel<<<(192 * 64 + 255) / 256, 256>>>(gru_W_hh, WhhT, 192, 64);

    // ---- relation: posted (lane -> intersection) ----
    compute_ad_kernel<<<(NINT + 63) / 64, 256>>>(e_int, Mfold, ad_, NINT);
    zero_kernel<<<(NINT * 4 + 255) / 256, 256>>>(den, NINT * 4);
    gemm_kernel<true, true, false><<<dim3(4, (NLANE + 63) / 64), 256>>>(
        e_lane, Wsrc_po, hs, att_src_po, as_, NLANE, 64, 256);
    edge_softmax_kernel<<<(EPO + 255) / 256, 256>>>(src_po, dst_po, as_, ad_, ex, den, EPO);
    recip_kernel<<<(NINT * 4 + 255) / 256, 256>>>(den, NINT * 4);
    edge_aggregate_kernel<<<EPO, 256>>>(src_po, dst_po, hs, ex, den, accum);

    // ---- relation: adjacency (intersection -> intersection) ----
    compute_ad_kernel<<<(NINT + 63) / 64, 256>>>(e_int, Mfold + 256, ad_, NINT);
    zero_kernel<<<(NINT * 4 + 255) / 256, 256>>>(den, NINT * 4);
    gemm_kernel<true, true, false><<<dim3(4, (NINT + 63) / 64), 256>>>(
        e_int, Wsrc_adj, hs, att_src_adj, as_, NINT, 64, 256);
    edge_softmax_kernel<<<(EADJ + 255) / 256, 256>>>(src_adj, dst_adj, as_, ad_, ex, den, EADJ);
    recip_kernel<<<(NINT * 4 + 255) / 256, 256>>>(den, NINT * 4);
    edge_aggregate_kernel<<<EADJ, 256>>>(src_adj, dst_adj, hs, ex, den, accum);

    // ---- GRU (relu fused into A-load of gi GEMM) ----
    gemm_kernel<true, false, true><<<dim3(3, (NINT + 63) / 64), 256>>>(
        accum, WihT, gi, nullptr, nullptr, NINT, 256, 192);
    gemm_kernel<true, false, false><<<dim3(3, (NINT + 63) / 64), 256>>>(
        h0, WhhT, gh, nullptr, nullptr, NINT, 64, 192);
    gru_kernel<<<(NINT * 64 + 255) / 256, 256>>>(gi, gh, gru_b_ih, gru_b_hh, h0, hnew, NINT);

    // ---- heads ----
    heads_kernel<<<(NINT + 7) / 8, 256>>>(hnew, W_pi, b_pi, W_v, b_v, logits, value, NINT);
}

// round 3
// speedup vs baseline: 2.0543x; 2.0543x over previous
#include <cuda_runtime.h>

#define NINT 50000
#define NLANE 400000
#define EPO 400000
#define EADJ 200000
#define CH 64
#define HC 256
#define G3 192

// ---------------- scratch (static device globals; no allocation) ----------------
__device__ float g_e_int[(size_t)NINT * CH];
__device__ float g_e_lane[(size_t)NLANE * CH];
__device__ float g_U[(size_t)2 * NINT * HC];        // [U_po | U_adj]
__device__ float g_den[(size_t)2 * NINT * 4];       // [den_po | den_adj]
__device__ float g_ex_po[(size_t)EPO * 4];
__device__ float g_ex_adj[(size_t)EADJ * 4];
__device__ float g_as_po[(size_t)NLANE * 4];
__device__ float g_small[(size_t)3 * NINT * 4];     // ad_po | ad_adj | as_adj
__device__ float g_inter[(size_t)NINT * HC];
__device__ float g_gi[(size_t)NINT * G3];
__device__ float g_gh[(size_t)NINT * G3];
__device__ float g_WihT[HC * G3];
__device__ float g_WhhT[CH * G3];
__device__ float g_Mfold[4 * 256];                  // [srcpo|dstpo|srcadj|dstadj], [k*4+h]

// ---------------- encoders: E = relu(X[M,K] @ W[K,64] + b) ----------------
template <int K>
__global__ void encoder_kernel(const float* __restrict__ X, const float* __restrict__ W,
                               const float* __restrict__ b, float* __restrict__ Eo, int M) {
    __shared__ float Ws[K * 64];
    __shared__ float bs[64];
    __shared__ float Xs[4][K];
    int t = threadIdx.x;
    for (int i = t; i < K * 64; i += 256) Ws[i] = W[i];
    if (t < 64) bs[t] = b[t];
    int row0 = blockIdx.x * 4;
    for (int i = t; i < 4 * K; i += 256) {
        int r = i / K, k = i % K;
        int gr = row0 + r;
        Xs[r][k] = (gr < M) ? X[(size_t)gr * K + k] : 0.f;
    }
    __syncthreads();
    int r = t >> 6, c = t & 63;
    float s = bs[c];
#pragma unroll
    for (int k = 0; k < K; k++) s += Xs[r][k] * Ws[k * 64 + c];
    int gr = row0 + r;
    if (gr < M) Eo[(size_t)gr * 64 + c] = fmaxf(s, 0.f);
}

// ---------------- fold all 4 att matrices: Mout[mat][k*4+h] = sum_c W[k,h*64+c]*att[h,c] ----
__global__ void fold_all_kernel(const float* __restrict__ W0, const float* __restrict__ a0,
                                const float* __restrict__ W1, const float* __restrict__ a1,
                                const float* __restrict__ W2, const float* __restrict__ a2,
                                const float* __restrict__ W3, const float* __restrict__ a3,
                                float* __restrict__ Mout) {
    int mat = blockIdx.y;
    const float* W = (mat == 0) ? W0 : (mat == 1) ? W1 : (mat == 2) ? W2 : W3;
    const float* a = (mat == 0) ? a0 : (mat == 1) ? a1 : (mat == 2) ? a2 : a3;
    int warp = threadIdx.x >> 5, lane = threadIdx.x & 31;
    int o = blockIdx.x * 8 + warp;   // 0..255
    int k = o >> 2, h = o & 3;
    float s = W[k * 256 + h * 64 + lane] * a[h * 64 + lane] +
              W[k * 256 + h * 64 + lane + 32] * a[h * 64 + lane + 32];
    s += __shfl_xor_sync(0xffffffffu, s, 16);
    s += __shfl_xor_sync(0xffffffffu, s, 8);
    s += __shfl_xor_sync(0xffffffffu, s, 4);
    s += __shfl_xor_sync(0xffffffffu, s, 2);
    s += __shfl_xor_sync(0xffffffffu, s, 1);
    if (lane == 0) Mout[mat * 256 + k * 4 + h] = s;
}

// ---------------- scores: out[M,4] = E[M,64] @ Mfold[64,4] ----------------
__global__ void compute_ad_kernel(const float* __restrict__ E, const float* __restrict__ Mm,
                                  float* __restrict__ ad, int M) {
    __shared__ float Es[64][65];
    __shared__ float Ms[256];
    int t = threadIdx.x;
    Ms[t] = Mm[t];
    int row0 = blockIdx.x * 64;
#pragma unroll
    for (int it = 0; it < 16; it++) {
        int idx = it * 256 + t;
        int k = idx & 63, r = idx >> 6;
        int gr = row0 + r;
        Es[r][k] = (gr < M) ? E[(size_t)gr * 64 + k] : 0.f;
    }
    __syncthreads();
    int r = t >> 2, h = t & 3;
    float s = 0.f;
#pragma unroll
    for (int k = 0; k < 64; k++) s += Es[r][k] * Ms[k * 4 + h];
    int gr = row0 + r;
    if (gr < M) ad[(size_t)gr * 4 + h] = s;
}

// ---------------- vectorized zero ----------------
__global__ void zero4_kernel(float4* __restrict__ p, int n4) {
    int i = blockIdx.x * blockDim.x + threadIdx.x;
    if (i < n4) p[i] = make_float4(0.f, 0.f, 0.f, 0.f);
}

// ---------------- edge softmax numerator: ex = exp(lrelu(a_s[src]+a_d[dst])); den += ex ----
__global__ void edge_softmax_kernel(const int* __restrict__ src, const int* __restrict__ dst,
                                    const float* __restrict__ as_, const float* __restrict__ ad_,
                                    float* __restrict__ ex, float* __restrict__ den, int E) {
    int e = blockIdx.x * blockDim.x + threadIdx.x;
    if (e >= E) return;
    int s = src[e], d = dst[e];
    float4 A = *(const float4*)&as_[(size_t)s * 4];
    float4 D = *(const float4*)&ad_[(size_t)d * 4];
    float v0 = A.x + D.x, v1 = A.y + D.y, v2 = A.z + D.z, v3 = A.w + D.w;
    v0 = (v0 > 0.f) ? v0 : 0.2f * v0;
    v1 = (v1 > 0.f) ? v1 : 0.2f * v1;
    v2 = (v2 > 0.f) ? v2 : 0.2f * v2;
    v3 = (v3 > 0.f) ? v3 : 0.2f * v3;
    float e0 = __expf(v0), e1 = __expf(v1), e2 = __expf(v2), e3 = __expf(v3);
    *(float4*)&ex[(size_t)e * 4] = make_float4(e0, e1, e2, e3);
    float* p = &den[(size_t)d * 4];
    asm volatile("red.global.add.v4.f32 [%0], {%1, %2, %3, %4};"
                 :: "l"(p), "f"(e0), "f"(e1), "f"(e2), "f"(e3) : "memory");
}

__global__ void recip_kernel(float* __restrict__ den, int n) {
    int i = blockIdx.x * blockDim.x + threadIdx.x;
    if (i < n) {
        float d = den[i];
        den[i] = (d > 0.f) ? 1.f / d : 0.f;
    }
}

// ---------------- edge scatter into U: U[dst,h,k] += w * feat[src,k] ----------------
// 256 threads = 4 edges; 64 threads per edge (h = t>>4, k4 = (t&15)*4)
__global__ void scatter_kernel(const int* __restrict__ src, const int* __restrict__ dst,
                               const float* __restrict__ feat, const float* __restrict__ ex,
                               const float* __restrict__ rden, float* __restrict__ U, int E) {
    int eg = threadIdx.x >> 6;
    int t64 = threadIdx.x & 63;
    int e = blockIdx.x * 4 + eg;
    if (e >= E) return;
    int s = src[e], d = dst[e];
    int h = t64 >> 4, k4 = (t64 & 15) << 2;
    float w = ex[(size_t)e * 4 + h] * rden[(size_t)d * 4 + h];
    float4 v = *(const float4*)&feat[(size_t)s * 64 + k4];
    float* p = &U[(size_t)d * 256 + h * 64 + k4];
    asm volatile("red.global.add.v4.f32 [%0], {%1, %2, %3, %4};"
                 :: "l"(p), "f"(v.x * w), "f"(v.y * w), "f"(v.z * w), "f"(v.w * w) : "memory");
}

// ---------------- fused dual block-diagonal GEMM + bias + relu ----------------
// inter[m, h*64+c] = relu( U_po[m,h,:]@Wpo[:,h*64+c] + U_adj[m,h,:]@Wadj[:,h*64+c] + bpo + badj )
// grid (4 heads, M/64). 256 threads, 4x4 micro-tile. Dynamic smem 66048 B.
__global__ void inter_kernel(const float* __restrict__ Upo, const float* __restrict__ Uadj,
                             const float* __restrict__ Wpo, const float* __restrict__ Wadj,
                             const float* __restrict__ bpo, const float* __restrict__ badj,
                             float* __restrict__ inter, int M) {
    extern __shared__ float sm[];
    float* Ap = sm;                        // [64][65] k-major: Ap[k*65+m]
    float* Aa = sm + 64 * 65;              // [64][65]
    float* Bp = sm + 2 * 64 * 65;          // [64][64]: Bp[k*64+c]
    float* Ba = sm + 2 * 64 * 65 + 64 * 64;
    int h = blockIdx.x;
    int m0 = blockIdx.y << 6;
    int t = threadIdx.x;
    int tx = t & 15, ty = t >> 4;

#pragma unroll
    for (int it = 0; it < 16; it++) {
        int idx = it * 256 + t;
        int k = idx >> 6, c = idx & 63;
        Bp[k * 64 + c] = Wpo[k * 256 + h * 64 + c];
        Ba[k * 64 + c] = Wadj[k * 256 + h * 64 + c];
    }
#pragma unroll
    for (int it = 0; it < 16; it++) {
        int idx = it * 256 + t;
        int k = idx & 63, m = idx >> 6;
        int gm = m0 + m;
        float vp = 0.f, va = 0.f;
        if (gm < M) {
            vp = Upo[(size_t)gm * 256 + h * 64 + k];
            va = Uadj[(size_t)gm * 256 + h * 64 + k];
        }
        Ap[k * 65 + m] = vp;
        Aa[k * 65 + m] = va;
    }
    __syncthreads();

    float acc[4][4];
#pragma unroll
    for (int i = 0; i < 4; i++)
#pragma unroll
        for (int j = 0; j < 4; j++) acc[i][j] = 0.f;

#pragma unroll 4
    for (int k = 0; k < 64; k++) {
        float4 bp = *(const float4*)&Bp[k * 64 + (tx << 2)];
        float4 ba = *(const float4*)&Ba[k * 64 + (tx << 2)];
#pragma unroll
        for (int i = 0; i < 4; i++) {
            float ap = Ap[k * 65 + (ty << 2) + i];
            float aa = Aa[k * 65 + (ty << 2) + i];
            acc[i][0] += ap * bp.x + aa * ba.x;
            acc[i][1] += ap * bp.y + aa * ba.y;
            acc[i][2] += ap * bp.z + aa * ba.z;
            acc[i][3] += ap * bp.w + aa * ba.w;
        }
    }

    int cbase = h * 64 + (tx << 2);
    float b0 = bpo[cbase + 0] + badj[cbase + 0];
    float b1 = bpo[cbase + 1] + badj[cbase + 1];
    float b2 = bpo[cbase + 2] + badj[cbase + 2];
    float b3 = bpo[cbase + 3] + badj[cbase + 3];
#pragma unroll
    for (int i = 0; i < 4; i++) {
        int gm = m0 + (ty << 2) + i;
        if (gm < M) {
            float4 o;
            o.x = fmaxf(acc[i][0] + b0, 0.f);
            o.y = fmaxf(acc[i][1] + b1, 0.f);
            o.z = fmaxf(acc[i][2] + b2, 0.f);
            o.w = fmaxf(acc[i][3] + b3, 0.f);
            *(float4*)&inter[(size_t)gm * 256 + cbase] = o;
        }
    }
}

// ---------------- generic GEMM: C[M,N] = A[M,K] @ B[K,N] (64x64 tile, 4x4 micro) ----------
__global__ void gemm_kernel(const float* __restrict__ A, const float* __restrict__ B,
                            float* __restrict__ C, int M, int K, int N) {
    __shared__ float As[64][65];
    __shared__ float Bs[64][64];
    int t = threadIdx.x;
    int tx = t & 15, ty = t >> 4;
    int m0 = blockIdx.y << 6, n0 = blockIdx.x << 6;
    float acc[4][4];
#pragma unroll
    for (int i = 0; i < 4; i++)
#pragma unroll
        for (int j = 0; j < 4; j++) acc[i][j] = 0.f;

    for (int k0 = 0; k0 < K; k0 += 64) {
#pragma unroll
        for (int it = 0; it < 16; it++) {
            int idx = it * 256 + t;
            int k = idx & 63, m = idx >> 6;
            int gm = m0 + m;
            As[k][m] = (gm < M) ? A[(size_t)gm * K + k0 + k] : 0.f;
        }
#pragma unroll
        for (int it = 0; it < 16; it++) {
            int idx = it * 256 + t;
            int n = idx & 63, k = idx >> 6;
            Bs[k][n] = B[(size_t)(k0 + k) * N + n0 + n];
        }
        __syncthreads();
#pragma unroll 8
        for (int k = 0; k < 64; k++) {
            float4 bv = *(const float4*)&Bs[k][tx << 2];
            float a0 = As[k][(ty << 2) + 0];
            float a1 = As[k][(ty << 2) + 1];
            float a2 = As[k][(ty << 2) + 2];
            float a3 = As[k][(ty << 2) + 3];
            acc[0][0] += a0 * bv.x; acc[0][1] += a0 * bv.y; acc[0][2] += a0 * bv.z; acc[0][3] += a0 * bv.w;
            acc[1][0] += a1 * bv.x; acc[1][1] += a1 * bv.y; acc[1][2] += a1 * bv.z; acc[1][3] += a1 * bv.w;
            acc[2][0] += a2 * bv.x; acc[2][1] += a2 * bv.y; acc[2][2] += a2 * bv.z; acc[2][3] += a2 * bv.w;
            acc[3][0] += a3 * bv.x; acc[3][1] += a3 * bv.y; acc[3][2] += a3 * bv.z; acc[3][3] += a3 * bv.w;
        }
        __syncthreads();
    }
#pragma unroll
    for (int i = 0; i < 4; i++) {
        int gm = m0 + (ty << 2) + i;
        if (gm < M)
            *(float4*)&C[(size_t)gm * N + n0 + (tx << 2)] =
                make_float4(acc[i][0], acc[i][1], acc[i][2], acc[i][3]);
    }
}

// ---------------- transpose ----------------
__global__ void transpose_kernel(const float* __restrict__ W, float* __restrict__ Wt, int R, int C) {
    int i = blockIdx.x * blockDim.x + threadIdx.x;
    if (i < R * C) {
        int r = i / C, c = i % C;
        Wt[c * R + r] = W[i];
    }
}

// ---------------- GRU elementwise ----------------
__global__ void gru_kernel(const float* __restrict__ gi, const float* __restrict__ gh,
                           const float* __restrict__ bih, const float* __restrict__ bhh,
                           const float* __restrict__ h0, float* __restrict__ hnew, int M) {
    int idx = blockIdx.x * blockDim.x + threadIdx.x;
    if (idx >= M * 64) return;
    int row = idx >> 6, c = idx & 63;
    float ir = gi[(size_t)row * 192 + c] + bih[c];
    float iz = gi[(size_t)row * 192 + 64 + c] + bih[64 + c];
    float in = gi[(size_t)row * 192 + 128 + c] + bih[128 + c];
    float hr = gh[(size_t)row * 192 + c] + bhh[c];
    float hz = gh[(size_t)row * 192 + 64 + c] + bhh[64 + c];
    float hn = gh[(size_t)row * 192 + 128 + c] + bhh[128 + c];
    float r = 1.f / (1.f + __expf(-(ir + hr)));
    float z = 1.f / (1.f + __expf(-(iz + hz)));
    float n = tanhf(in + r * hn);
    hnew[idx] = (1.f - z) * n + z * h0[idx];
}

// ---------------- output heads ----------------
__global__ void heads_kernel(const float* __restrict__ hn, const float* __restrict__ Wpi,
                             const float* __restrict__ bpi, const float* __restrict__ Wv,
                             const float* __restrict__ bv, float* __restrict__ logits,
                             float* __restrict__ value, int M) {
    __shared__ float Wp[64 * 8];
    __shared__ float Wvv[64];
    int t = threadIdx.x;
    for (int i = t; i < 512; i += 256) Wp[i] = Wpi[i];
    if (t < 64) Wvv[t] = Wv[t];
    __syncthreads();
    int warp = t >> 5, lane = t & 31;
    int row = blockIdx.x * 8 + warp;
    if (row >= M) return;
    float h1 = hn[(size_t)row * 64 + lane];
    float h2 = hn[(size_t)row * 64 + 32 + lane];
#pragma unroll
    for (int j = 0; j < 8; j++) {
        float p = h1 * Wp[lane * 8 + j] + h2 * Wp[(lane + 32) * 8 + j];
        p += __shfl_xor_sync(0xffffffffu, p, 16);
        p += __shfl_xor_sync(0xffffffffu, p, 8);
        p += __shfl_xor_sync(0xffffffffu, p, 4);
        p += __shfl_xor_sync(0xffffffffu, p, 2);
        p += __shfl_xor_sync(0xffffffffu, p, 1);
        if (lane == 0) logits[(size_t)row * 8 + j] = p + bpi[j];
    }
    float v = h1 * Wvv[lane] + h2 * Wvv[lane + 32];
    v += __shfl_xor_sync(0xffffffffu, v, 16);
    v += __shfl_xor_sync(0xffffffffu, v, 8);
    v += __shfl_xor_sync(0xffffffffu, v, 4);
    v += __shfl_xor_sync(0xffffffffu, v, 2);
    v += __shfl_xor_sync(0xffffffffu, v, 1);
    if (lane == 0) value[row] = v + bv[0];
}

// ---------------- launch ----------------
extern "C" void kernel_launch(void* const* d_in, const int* in_sizes, int n_in,
                              void* d_out, int out_size) {
    const float* x_int = (const float*)d_in[0];
    const float* x_lane = (const float*)d_in[1];
    const float* h0 = (const float*)d_in[2];
    const float* enc_int_W = (const float*)d_in[3];
    const float* enc_int_b = (const float*)d_in[4];
    const float* enc_lane_W = (const float*)d_in[5];
    const float* enc_lane_b = (const float*)d_in[6];
    const float* Wsrc_po = (const float*)d_in[7];
    const float* Wdst_po = (const float*)d_in[8];
    const float* att_src_po = (const float*)d_in[9];
    const float* att_dst_po = (const float*)d_in[10];
    const float* bias_po = (const float*)d_in[11];
    const float* Wsrc_adj = (const float*)d_in[12];
    const float* Wdst_adj = (const float*)d_in[13];
    const float* att_src_adj = (const float*)d_in[14];
    const float* att_dst_adj = (const float*)d_in[15];
    const float* bias_adj = (const float*)d_in[16];
    const float* gru_W_ih = (const float*)d_in[17];
    const float* gru_W_hh = (const float*)d_in[18];
    const float* gru_b_ih = (const float*)d_in[19];
    const float* gru_b_hh = (const float*)d_in[20];
    const float* W_pi = (const float*)d_in[21];
    const float* b_pi = (const float*)d_in[22];
    const float* W_v = (const float*)d_in[23];
    const float* b_v = (const float*)d_in[24];
    const int* src_po = (const int*)d_in[25];
    const int* dst_po = (const int*)d_in[26];
    const int* src_adj = (const int*)d_in[27];
    const int* dst_adj = (const int*)d_in[28];

    float* out = (float*)d_out;
    float* logits = out;
    float* value = out + (size_t)NINT * 8;
    float* hnew = out + (size_t)NINT * 9;

    float *e_int, *e_lane, *U, *den, *ex_po, *ex_adj, *as_po, *small, *inter, *gi, *gh, *WihT, *WhhT, *Mfold;
    cudaGetSymbolAddress((void**)&e_int, g_e_int);
    cudaGetSymbolAddress((void**)&e_lane, g_e_lane);
    cudaGetSymbolAddress((void**)&U, g_U);
    cudaGetSymbolAddress((void**)&den, g_den);
    cudaGetSymbolAddress((void**)&ex_po, g_ex_po);
    cudaGetSymbolAddress((void**)&ex_adj, g_ex_adj);
    cudaGetSymbolAddress((void**)&as_po, g_as_po);
    cudaGetSymbolAddress((void**)&small, g_small);
    cudaGetSymbolAddress((void**)&inter, g_inter);
    cudaGetSymbolAddress((void**)&gi, g_gi);
    cudaGetSymbolAddress((void**)&gh, g_gh);
    cudaGetSymbolAddress((void**)&WihT, g_WihT);
    cudaGetSymbolAddress((void**)&WhhT, g_WhhT);
    cudaGetSymbolAddress((void**)&Mfold, g_Mfold);

    float* U_po = U;
    float* U_adj = U + (size_t)NINT * HC;
    float* den_po = den;
    float* den_adj = den + (size_t)NINT * 4;
    float* ad_po = small;
    float* ad_adj = small + (size_t)NINT * 4;
    float* as_adj = small + (size_t)2 * NINT * 4;

    cudaFuncSetAttribute(inter_kernel, cudaFuncAttributeMaxDynamicSharedMemorySize, 67072);

    // encoders
    encoder_kernel<16><<<(NINT + 3) / 4, 256>>>(x_int, enc_int_W, enc_int_b, e_int, NINT);
    encoder_kernel<12><<<(NLANE + 3) / 4, 256>>>(x_lane, enc_lane_W, enc_lane_b, e_lane, NLANE);

    // prep
    fold_all_kernel<<<dim3(32, 4), 256>>>(Wsrc_po, att_src_po, Wdst_po, att_dst_po,
                                          Wsrc_adj, att_src_adj, Wdst_adj, att_dst_adj, Mfold);
    transpose_kernel<<<(192 * 256 + 255) / 256, 256>>>(gru_W_ih, WihT, 192, 256);
    transpose_kernel<<<(192 * 64 + 255) / 256, 256>>>(gru_W_hh, WhhT, 192, 64);
    zero4_kernel<<<(2 * NINT * HC / 4 + 255) / 256, 256>>>((float4*)U, 2 * NINT * HC / 4);
    zero4_kernel<<<(2 * NINT * 4 / 4 + 255) / 256, 256>>>((float4*)den, 2 * NINT * 4 / 4);

    // attention scores (all via folded 64x4 matvec)
    compute_ad_kernel<<<(NLANE + 63) / 64, 256>>>(e_lane, Mfold + 0 * 256, as_po, NLANE);
    compute_ad_kernel<<<(NINT + 63) / 64, 256>>>(e_int, Mfold + 1 * 256, ad_po, NINT);
    compute_ad_kernel<<<(NINT + 63) / 64, 256>>>(e_int, Mfold + 2 * 256, as_adj, NINT);
    compute_ad_kernel<<<(NINT + 63) / 64, 256>>>(e_int, Mfold + 3 * 256, ad_adj, NINT);

    // edge softmax
    edge_softmax_kernel<<<(EPO + 255) / 256, 256>>>(src_po, dst_po, as_po, ad_po, ex_po, den_po, EPO);
    edge_softmax_kernel<<<(EADJ + 255) / 256, 256>>>(src_adj, dst_adj, as_adj, ad_adj, ex_adj, den_adj, EADJ);
    recip_kernel<<<(2 * NINT * 4 + 255) / 256, 256>>>(den, 2 * NINT * 4);

    // edge scatter into U-space (64-dim, pre-W)
    scatter_kernel<<<(EPO + 3) / 4, 256>>>(src_po, dst_po, e_lane, ex_po, den_po, U_po, EPO);
    scatter_kernel<<<(EADJ + 3) / 4, 256>>>(src_adj, dst_adj, e_int, ex_adj, den_adj, U_adj, EADJ);

    // fused dual block-diagonal GEMM + bias + relu
    inter_kernel<<<dim3(4, (NINT + 63) / 64), 256, 67072>>>(
        U_po, U_adj, Wsrc_po, Wsrc_adj, bias_po, bias_adj, inter, NINT);

    // GRU
    gemm_kernel<<<dim3(3, (NINT + 63) / 64), 256>>>(inter, WihT, gi, NINT, 256, 192);
    gemm_kernel<<<dim3(3, (NINT + 63) / 64), 256>>>(h0, WhhT, gh, NINT, 64, 192);
    gru_kernel<<<(NINT * 64 + 255) / 256, 256>>>(gi, gh, gru_b_ih, gru_b_hh, h0, hnew, NINT);

    // heads
    heads_kernel<<<(NINT + 7) / 8, 256>>>(hnew, W_pi, b_pi, W_v, b_v, logits, value, NINT);
}